// round 10
// baseline (speedup 1.0000x reference)
#include <cuda_runtime.h>

// CMFMLoss: B=64, T=1024, D=256. Single fused streaming kernel.
// Identity: sum_{i!=j} cross_cos[i,j]
//   = (1/T) * [ sum_t <sum_i vn[i,t,:], sum_j an[j,t,:]>  -  sum_{b,t} cos_bt ]
// 128-thread blocks (4 warps x 16 rows); DEPTH-2 register pipeline: rows i+1
// and i+2 loads are in flight during row i's shuffle/rsqrt chain.

#define Bb 64
#define Tt 1024
#define Dd 256
#define NBLK 1024
#define EPS2 1e-16f

__device__ float    g_cr[NBLK];
__device__ float    g_cp[NBLK];
__device__ float    g_ca[NBLK];
__device__ unsigned g_done = 0;

__device__ __forceinline__ float dot8(const float4& x0, const float4& x1,
                                      const float4& y0, const float4& y1) {
    float s = x0.x * y0.x;
    s = fmaf(x0.y, y0.y, s); s = fmaf(x0.z, y0.z, s); s = fmaf(x0.w, y0.w, s);
    s = fmaf(x1.x, y1.x, s); s = fmaf(x1.y, y1.y, s);
    s = fmaf(x1.z, y1.z, s); s = fmaf(x1.w, y1.w, s);
    return s;
}

__device__ __forceinline__ float bfly_add(float v) {
    #pragma unroll
    for (int off = 16; off > 0; off >>= 1)
        v += __shfl_xor_sync(0xffffffffu, v, off);
    return v;
}

__global__ void __launch_bounds__(128, 5)
cmfm_fused(const float* __restrict__ fv,
           const float* __restrict__ fa,
           const long long* __restrict__ labels,
           float* __restrict__ out)
{
    const int t    = blockIdx.x;
    const int lane = threadIdx.x & 31;
    const int w    = threadIdx.x >> 5;   // warp 0..3

    __shared__ float s_sv[4][Dd];
    __shared__ float s_sa[4][Dd];
    __shared__ float s_cp[4];
    __shared__ float s_ca[4];
    __shared__ float s_red[4];
    __shared__ int   s_last;

    // One label LDG per lane; lane j holds weight of row (w*16 + (j&15)).
    const float wb_mine = (labels[w * 16 + (lane & 15)] == 0) ? 1.0f : 0.0f;

    float sv0=0.f,sv1=0.f,sv2=0.f,sv3=0.f,sv4=0.f,sv5=0.f,sv6=0.f,sv7=0.f;
    float sa0=0.f,sa1=0.f,sa2=0.f,sa3=0.f,sa4=0.f,sa5=0.f,sa6=0.f,sa7=0.f;
    float c_all = 0.f, c_pos = 0.f;     // per-lane partial cosine sums

    const size_t row0 = ((size_t)(w * 16) * Tt + t) * Dd;
    const size_t rstep = (size_t)Tt * Dd;   // +1 in b

    // Prologue: rows 0 and 1 in flight.
    const float4* v0p = reinterpret_cast<const float4*>(fv + row0);
    const float4* a0p = reinterpret_cast<const float4*>(fa + row0);
    const float4* v1p = reinterpret_cast<const float4*>(fv + row0 + rstep);
    const float4* a1p = reinterpret_cast<const float4*>(fa + row0 + rstep);
    float4 cv0 = v0p[lane], cv1 = v0p[lane + 32];
    float4 ca0 = a0p[lane], ca1 = a0p[lane + 32];
    float4 nv0 = v1p[lane], nv1 = v1p[lane + 32];
    float4 na0 = a1p[lane], na1 = a1p[lane + 32];

    #pragma unroll
    for (int i = 0; i < 16; ++i) {
        // Issue row i+2 loads FIRST (depth-2 lookahead).
        float4 qv0, qv1, qa0, qa1;
        if (i < 14) {
            const float4* vq = reinterpret_cast<const float4*>(fv + row0 + (size_t)(i + 2) * rstep);
            const float4* aq = reinterpret_cast<const float4*>(fa + row0 + (size_t)(i + 2) * rstep);
            qv0 = vq[lane]; qv1 = vq[lane + 32];
            qa0 = aq[lane]; qa1 = aq[lane + 32];
        }

        float nv = dot8(cv0, cv1, cv0, cv1);
        float na = dot8(ca0, ca1, ca0, ca1);
        const float dtp = dot8(cv0, cv1, ca0, ca1);   // per-lane partial

        #pragma unroll
        for (int off = 16; off > 0; off >>= 1) {
            nv += __shfl_xor_sync(0xffffffffu, nv, off);
            na += __shfl_xor_sync(0xffffffffu, na, off);
        }

        const float invV = rsqrtf(fmaxf(nv, EPS2));
        const float invA = rsqrtf(fmaxf(na, EPS2));

        sv0 = fmaf(cv0.x, invV, sv0); sv1 = fmaf(cv0.y, invV, sv1);
        sv2 = fmaf(cv0.z, invV, sv2); sv3 = fmaf(cv0.w, invV, sv3);
        sv4 = fmaf(cv1.x, invV, sv4); sv5 = fmaf(cv1.y, invV, sv5);
        sv6 = fmaf(cv1.z, invV, sv6); sv7 = fmaf(cv1.w, invV, sv7);
        sa0 = fmaf(ca0.x, invA, sa0); sa1 = fmaf(ca0.y, invA, sa1);
        sa2 = fmaf(ca0.z, invA, sa2); sa3 = fmaf(ca0.w, invA, sa3);
        sa4 = fmaf(ca1.x, invA, sa4); sa5 = fmaf(ca1.y, invA, sa5);
        sa6 = fmaf(ca1.z, invA, sa6); sa7 = fmaf(ca1.w, invA, sa7);

        // Per-row label weight via shuffle (no memory access).
        const float wb = __shfl_sync(0xffffffffu, wb_mine, i);
        const float c  = dtp * (invV * invA);
        c_all += c;
        c_pos = fmaf(c, wb, c_pos);

        // Rotate pipeline buffers (renamed away under full unroll).
        cv0 = nv0; cv1 = nv1; ca0 = na0; ca1 = na1;
        nv0 = qv0; nv1 = qv1; na0 = qa0; na1 = qa1;
    }

    // Warp totals for the cosine sums.
    c_all = bfly_add(c_all);
    c_pos = bfly_add(c_pos);

    {
        float4* svp = reinterpret_cast<float4*>(s_sv[w]);
        float4* sap = reinterpret_cast<float4*>(s_sa[w]);
        svp[lane]      = make_float4(sv0, sv1, sv2, sv3);
        svp[lane + 32] = make_float4(sv4, sv5, sv6, sv7);
        sap[lane]      = make_float4(sa0, sa1, sa2, sa3);
        sap[lane + 32] = make_float4(sa4, sa5, sa6, sa7);
        if (lane == 0) { s_cp[w] = c_pos; s_ca[w] = c_all; }
    }
    __syncthreads();

    // <Sv_t, Sa_t> across the 4 warp partials; each thread covers 2 d-columns.
    const int d0 = threadIdx.x;
    const int d1 = threadIdx.x + 128;
    float tv0 = 0.f, ta0 = 0.f, tv1 = 0.f, ta1 = 0.f;
    #pragma unroll
    for (int ww = 0; ww < 4; ++ww) {
        tv0 += s_sv[ww][d0]; ta0 += s_sa[ww][d0];
        tv1 += s_sv[ww][d1]; ta1 += s_sa[ww][d1];
    }
    const float prod = bfly_add(fmaf(tv1, ta1, tv0 * ta0));
    if (lane == 0) s_red[w] = prod;
    __syncthreads();

    // Publish block partials; last block performs the final reduce.
    if (threadIdx.x == 0) {
        float cr = 0.f, cpt = 0.f, cat = 0.f;
        #pragma unroll
        for (int ww = 0; ww < 4; ++ww) {
            cr  += s_red[ww];
            cpt += s_cp[ww];
            cat += s_ca[ww];
        }
        g_cr[t] = cr;
        g_cp[t] = cpt;
        g_ca[t] = cat;
        __threadfence();
        const unsigned old = atomicAdd(&g_done, 1u);
        s_last = (old == NBLK - 1) ? 1 : 0;
    }
    __syncthreads();
    if (!s_last) return;

    // ---- Final reduction (one block, deterministic order) ----
    {
        float cr = 0.f, cpr = 0.f, car = 0.f;
        #pragma unroll
        for (int k = 0; k < NBLK / 128; ++k) {
            const int i = threadIdx.x + k * 128;
            cr += g_cr[i]; cpr += g_cp[i]; car += g_ca[i];
        }
        cr  = bfly_add(cr);
        cpr = bfly_add(cpr);
        car = bfly_add(car);
        if (lane == 0) { s_red[w] = cr; s_cp[w] = cpr; s_ca[w] = car; }
        __syncthreads();

        if (threadIdx.x == 0) {
            float Cr = 0.f, Sp = 0.f, Sa = 0.f;
            #pragma unroll
            for (int ww = 0; ww < 4; ++ww) { Cr += s_red[ww]; Sp += s_cp[ww]; Sa += s_ca[ww]; }
            const float Sn = Sa - Sp;

            int npos = 0;
            for (int b = 0; b < Bb; ++b) npos += (labels[b] == 0) ? 1 : 0;
            const float fpos = (float)npos;
            const float fneg = (float)(Bb - npos);

            const float loss_pos = 2.0f * (fpos * (float)Tt - Sp);
            const float loss_neg = 2.0f * Sn + (Cr - Sa) / (float)Tt;

            const float cnt_pos = fpos * (float)Tt;
            const float cnt_neg = fneg * (float)Tt + (float)(Bb * (Bb - 1));

            float loss = 0.f;
            if (cnt_pos > 0.f) loss += loss_pos / fmaxf(cnt_pos, 1.0f);
            if (cnt_neg > 0.f) loss += loss_neg / fmaxf(cnt_neg, 1.0f);
            out[0] = loss;

            g_done = 0;   // self-reset for next (graph-replayed) call
        }
    }
}

extern "C" void kernel_launch(void* const* d_in, const int* in_sizes, int n_in,
                              void* d_out, int out_size)
{
    const float*     fv     = (const float*)d_in[0];
    const float*     fa     = (const float*)d_in[1];
    const long long* labels = (const long long*)d_in[2];
    float*           out    = (float*)d_out;

    (void)in_sizes; (void)n_in; (void)out_size;

    cmfm_fused<<<NBLK, 128>>>(fv, fa, labels, out);
}

// round 11
// speedup vs baseline: 1.0429x; 1.0429x over previous
#include <cuda_runtime.h>
#include <cstdint>

// CMFMLoss: B=64, T=1024, D=256. Single fused streaming kernel.
// Identity: sum_{i!=j} cross_cos[i,j]
//   = (1/T) * [ sum_t <sum_i vn[i,t,:], sum_j an[j,t,:]>  -  sum_{b,t} cos_bt ]
// 128-thread blocks (4 warps x 16 rows), depth-1 register pipeline (R9) PLUS
// sv/sa accumulators moved to per-warp SMEM (inline-asm RMW so ptxas cannot
// promote them) -> ~16 fewer regs -> 8 CTAs/SM at the same pipeline depth.

#define Bb 64
#define Tt 1024
#define Dd 256
#define NBLK 1024
#define EPS2 1e-16f

__device__ float    g_cr[NBLK];
__device__ float    g_cp[NBLK];
__device__ float    g_ca[NBLK];
__device__ unsigned g_done = 0;

__device__ __forceinline__ float dot8(const float4& x0, const float4& x1,
                                      const float4& y0, const float4& y1) {
    float s = x0.x * y0.x;
    s = fmaf(x0.y, y0.y, s); s = fmaf(x0.z, y0.z, s); s = fmaf(x0.w, y0.w, s);
    s = fmaf(x1.x, y1.x, s); s = fmaf(x1.y, y1.y, s);
    s = fmaf(x1.z, y1.z, s); s = fmaf(x1.w, y1.w, s);
    return s;
}

__device__ __forceinline__ float bfly_add(float v) {
    #pragma unroll
    for (int off = 16; off > 0; off >>= 1)
        v += __shfl_xor_sync(0xffffffffu, v, off);
    return v;
}

// SMEM vector RMW: acc[0..3] += q * s. Opaque to ptxas (no reg promotion).
__device__ __forceinline__ void smem_rmw4(uint32_t addr, float4 q, float s) {
    float r0, r1, r2, r3;
    asm volatile("ld.shared.v4.f32 {%0,%1,%2,%3}, [%4];"
                 : "=f"(r0), "=f"(r1), "=f"(r2), "=f"(r3) : "r"(addr));
    r0 = fmaf(q.x, s, r0); r1 = fmaf(q.y, s, r1);
    r2 = fmaf(q.z, s, r2); r3 = fmaf(q.w, s, r3);
    asm volatile("st.shared.v4.f32 [%0], {%1,%2,%3,%4};"
                 :: "r"(addr), "f"(r0), "f"(r1), "f"(r2), "f"(r3) : "memory");
}

__global__ void __launch_bounds__(128, 8)
cmfm_fused(const float* __restrict__ fv,
           const float* __restrict__ fa,
           const long long* __restrict__ labels,
           float* __restrict__ out)
{
    const int t    = blockIdx.x;
    const int lane = threadIdx.x & 31;
    const int w    = threadIdx.x >> 5;   // warp 0..3

    __shared__ float s_sv[4][Dd];
    __shared__ float s_sa[4][Dd];
    __shared__ float s_cp[4];
    __shared__ float s_ca[4];
    __shared__ float s_red[4];
    __shared__ int   s_last;

    // Zero the smem accumulators (each thread: 8 floats of sv + 8 of sa).
    {
        float4 z = make_float4(0.f, 0.f, 0.f, 0.f);
        float4* svz = reinterpret_cast<float4*>(&s_sv[0][0]);
        float4* saz = reinterpret_cast<float4*>(&s_sa[0][0]);
        svz[threadIdx.x]       = z;
        svz[threadIdx.x + 128] = z;
        saz[threadIdx.x]       = z;
        saz[threadIdx.x + 128] = z;
    }
    __syncthreads();

    // One label LDG per lane; lane j holds weight of row (w*16 + (j&15)).
    const float wb_mine = (labels[w * 16 + (lane & 15)] == 0) ? 1.0f : 0.0f;

    // SMEM addresses for this lane's accumulator slots.
    const uint32_t a_sv0 = (uint32_t)__cvta_generic_to_shared(&s_sv[w][4 * lane]);
    const uint32_t a_sv1 = a_sv0 + 128 * 4;   // d + 128
    const uint32_t a_sa0 = (uint32_t)__cvta_generic_to_shared(&s_sa[w][4 * lane]);
    const uint32_t a_sa1 = a_sa0 + 128 * 4;

    float c_all = 0.f, c_pos = 0.f;     // per-lane partial cosine sums

    const size_t row0  = ((size_t)(w * 16) * Tt + t) * Dd;
    const size_t rstep = (size_t)Tt * Dd;   // +1 in b

    // Prologue: load row 0.
    const float4* vp = reinterpret_cast<const float4*>(fv + row0);
    const float4* ap = reinterpret_cast<const float4*>(fa + row0);
    float4 cv0 = vp[lane], cv1 = vp[lane + 32];
    float4 ca0 = ap[lane], ca1 = ap[lane + 32];

    #pragma unroll
    for (int i = 0; i < 16; ++i) {
        // Depth-1 lookahead: row i+1 loads in flight during row i's chain.
        float4 pv0, pv1, pa0, pa1;
        if (i < 15) {
            const float4* vn_ = reinterpret_cast<const float4*>(fv + row0 + (size_t)(i + 1) * rstep);
            const float4* an_ = reinterpret_cast<const float4*>(fa + row0 + (size_t)(i + 1) * rstep);
            pv0 = vn_[lane]; pv1 = vn_[lane + 32];
            pa0 = an_[lane]; pa1 = an_[lane + 32];
        }

        float nv = dot8(cv0, cv1, cv0, cv1);
        float na = dot8(ca0, ca1, ca0, ca1);
        const float dtp = dot8(cv0, cv1, ca0, ca1);   // per-lane partial

        #pragma unroll
        for (int off = 16; off > 0; off >>= 1) {
            nv += __shfl_xor_sync(0xffffffffu, nv, off);
            na += __shfl_xor_sync(0xffffffffu, na, off);
        }

        const float invV = rsqrtf(fmaxf(nv, EPS2));
        const float invA = rsqrtf(fmaxf(na, EPS2));

        // Accumulate normalized rows into per-warp SMEM accumulators.
        smem_rmw4(a_sv0, cv0, invV);
        smem_rmw4(a_sv1, cv1, invV);
        smem_rmw4(a_sa0, ca0, invA);
        smem_rmw4(a_sa1, ca1, invA);

        // Per-row label weight via shuffle (no memory access).
        const float wb = __shfl_sync(0xffffffffu, wb_mine, i);
        const float c  = dtp * (invV * invA);
        c_all += c;
        c_pos = fmaf(c, wb, c_pos);

        // Rotate pipeline buffer.
        cv0 = pv0; cv1 = pv1; ca0 = pa0; ca1 = pa1;
    }

    // Warp totals for the cosine sums.
    c_all = bfly_add(c_all);
    c_pos = bfly_add(c_pos);
    if (lane == 0) { s_cp[w] = c_pos; s_ca[w] = c_all; }
    __syncthreads();

    // <Sv_t, Sa_t> across the 4 warp partials; each thread covers 2 d-columns.
    const int d0 = threadIdx.x;
    const int d1 = threadIdx.x + 128;
    float tv0 = 0.f, ta0 = 0.f, tv1 = 0.f, ta1 = 0.f;
    #pragma unroll
    for (int ww = 0; ww < 4; ++ww) {
        tv0 += s_sv[ww][d0]; ta0 += s_sa[ww][d0];
        tv1 += s_sv[ww][d1]; ta1 += s_sa[ww][d1];
    }
    const float prod = bfly_add(fmaf(tv1, ta1, tv0 * ta0));
    if (lane == 0) s_red[w] = prod;
    __syncthreads();

    // Publish block partials; last block performs the final reduce.
    if (threadIdx.x == 0) {
        float cr = 0.f, cpt = 0.f, cat = 0.f;
        #pragma unroll
        for (int ww = 0; ww < 4; ++ww) {
            cr  += s_red[ww];
            cpt += s_cp[ww];
            cat += s_ca[ww];
        }
        g_cr[t] = cr;
        g_cp[t] = cpt;
        g_ca[t] = cat;
        __threadfence();
        const unsigned old = atomicAdd(&g_done, 1u);
        s_last = (old == NBLK - 1) ? 1 : 0;
    }
    __syncthreads();
    if (!s_last) return;

    // ---- Final reduction (one block, deterministic order) ----
    {
        float cr = 0.f, cpr = 0.f, car = 0.f;
        #pragma unroll
        for (int k = 0; k < NBLK / 128; ++k) {
            const int i = threadIdx.x + k * 128;
            cr += g_cr[i]; cpr += g_cp[i]; car += g_ca[i];
        }
        cr  = bfly_add(cr);
        cpr = bfly_add(cpr);
        car = bfly_add(car);
        if (lane == 0) { s_red[w] = cr; s_cp[w] = cpr; s_ca[w] = car; }
        __syncthreads();

        if (threadIdx.x == 0) {
            float Cr = 0.f, Sp = 0.f, Sa = 0.f;
            #pragma unroll
            for (int ww = 0; ww < 4; ++ww) { Cr += s_red[ww]; Sp += s_cp[ww]; Sa += s_ca[ww]; }
            const float Sn = Sa - Sp;

            int npos = 0;
            for (int b = 0; b < Bb; ++b) npos += (labels[b] == 0) ? 1 : 0;
            const float fpos = (float)npos;
            const float fneg = (float)(Bb - npos);

            const float loss_pos = 2.0f * (fpos * (float)Tt - Sp);
            const float loss_neg = 2.0f * Sn + (Cr - Sa) / (float)Tt;

            const float cnt_pos = fpos * (float)Tt;
            const float cnt_neg = fneg * (float)Tt + (float)(Bb * (Bb - 1));

            float loss = 0.f;
            if (cnt_pos > 0.f) loss += loss_pos / fmaxf(cnt_pos, 1.0f);
            if (cnt_neg > 0.f) loss += loss_neg / fmaxf(cnt_neg, 1.0f);
            out[0] = loss;

            g_done = 0;   // self-reset for next (graph-replayed) call
        }
    }
}

extern "C" void kernel_launch(void* const* d_in, const int* in_sizes, int n_in,
                              void* d_out, int out_size)
{
    const float*     fv     = (const float*)d_in[0];
    const float*     fa     = (const float*)d_in[1];
    const long long* labels = (const long long*)d_in[2];
    float*           out    = (float*)d_out;

    (void)in_sizes; (void)n_in; (void)out_size;

    cmfm_fused<<<NBLK, 128>>>(fv, fa, labels, out);
}

// round 12
// speedup vs baseline: 1.1086x; 1.0631x over previous
#include <cuda_runtime.h>

// CMFMLoss: B=64, T=1024, D=256. Single fused streaming kernel.
// Identity: sum_{i!=j} cross_cos[i,j]
//   = (1/T) * [ sum_t <sum_i vn[i,t,:], sum_j an[j,t,:]>  -  sum_{b,t} cos_bt ]
// R9 shape (128 thr, 4 warps x 16 rows, depth-1 register pipeline) with
// __ldcs streaming loads (data is read exactly once -> evict-first policy).

#define Bb 64
#define Tt 1024
#define Dd 256
#define NBLK 1024
#define EPS2 1e-16f

__device__ float    g_cr[NBLK];
__device__ float    g_cp[NBLK];
__device__ float    g_ca[NBLK];
__device__ unsigned g_done = 0;

__device__ __forceinline__ float dot8(const float4& x0, const float4& x1,
                                      const float4& y0, const float4& y1) {
    float s = x0.x * y0.x;
    s = fmaf(x0.y, y0.y, s); s = fmaf(x0.z, y0.z, s); s = fmaf(x0.w, y0.w, s);
    s = fmaf(x1.x, y1.x, s); s = fmaf(x1.y, y1.y, s);
    s = fmaf(x1.z, y1.z, s); s = fmaf(x1.w, y1.w, s);
    return s;
}

__device__ __forceinline__ float bfly_add(float v) {
    #pragma unroll
    for (int off = 16; off > 0; off >>= 1)
        v += __shfl_xor_sync(0xffffffffu, v, off);
    return v;
}

__global__ void __launch_bounds__(128, 7)
cmfm_fused(const float* __restrict__ fv,
           const float* __restrict__ fa,
           const long long* __restrict__ labels,
           float* __restrict__ out)
{
    const int t    = blockIdx.x;
    const int lane = threadIdx.x & 31;
    const int w    = threadIdx.x >> 5;   // warp 0..3

    __shared__ float s_sv[4][Dd];
    __shared__ float s_sa[4][Dd];
    __shared__ float s_cp[4];
    __shared__ float s_ca[4];
    __shared__ float s_red[4];
    __shared__ int   s_last;

    // One label LDG per lane; lane j holds weight of row (w*16 + (j&15)).
    const float wb_mine = (labels[w * 16 + (lane & 15)] == 0) ? 1.0f : 0.0f;

    float sv0=0.f,sv1=0.f,sv2=0.f,sv3=0.f,sv4=0.f,sv5=0.f,sv6=0.f,sv7=0.f;
    float sa0=0.f,sa1=0.f,sa2=0.f,sa3=0.f,sa4=0.f,sa5=0.f,sa6=0.f,sa7=0.f;
    float c_all = 0.f, c_pos = 0.f;     // per-lane partial cosine sums

    const size_t row0 = ((size_t)(w * 16) * Tt + t) * Dd;
    const size_t rstep = (size_t)Tt * Dd;   // +1 in b

    // Prologue: load row 0 (streaming, evict-first).
    const float4* vp = reinterpret_cast<const float4*>(fv + row0);
    const float4* ap = reinterpret_cast<const float4*>(fa + row0);
    float4 cv0 = __ldcs(vp + lane), cv1 = __ldcs(vp + lane + 32);
    float4 ca0 = __ldcs(ap + lane), ca1 = __ldcs(ap + lane + 32);

    #pragma unroll
    for (int i = 0; i < 16; ++i) {
        float4 pv0, pv1, pa0, pa1;
        if (i < 15) {
            const float4* vn_ = reinterpret_cast<const float4*>(fv + row0 + (size_t)(i + 1) * rstep);
            const float4* an_ = reinterpret_cast<const float4*>(fa + row0 + (size_t)(i + 1) * rstep);
            pv0 = __ldcs(vn_ + lane); pv1 = __ldcs(vn_ + lane + 32);
            pa0 = __ldcs(an_ + lane); pa1 = __ldcs(an_ + lane + 32);
        }

        float nv = dot8(cv0, cv1, cv0, cv1);
        float na = dot8(ca0, ca1, ca0, ca1);
        const float dtp = dot8(cv0, cv1, ca0, ca1);   // per-lane partial

        #pragma unroll
        for (int off = 16; off > 0; off >>= 1) {
            nv += __shfl_xor_sync(0xffffffffu, nv, off);
            na += __shfl_xor_sync(0xffffffffu, na, off);
        }

        const float invV = rsqrtf(fmaxf(nv, EPS2));
        const float invA = rsqrtf(fmaxf(na, EPS2));

        sv0 = fmaf(cv0.x, invV, sv0); sv1 = fmaf(cv0.y, invV, sv1);
        sv2 = fmaf(cv0.z, invV, sv2); sv3 = fmaf(cv0.w, invV, sv3);
        sv4 = fmaf(cv1.x, invV, sv4); sv5 = fmaf(cv1.y, invV, sv5);
        sv6 = fmaf(cv1.z, invV, sv6); sv7 = fmaf(cv1.w, invV, sv7);
        sa0 = fmaf(ca0.x, invA, sa0); sa1 = fmaf(ca0.y, invA, sa1);
        sa2 = fmaf(ca0.z, invA, sa2); sa3 = fmaf(ca0.w, invA, sa3);
        sa4 = fmaf(ca1.x, invA, sa4); sa5 = fmaf(ca1.y, invA, sa5);
        sa6 = fmaf(ca1.z, invA, sa6); sa7 = fmaf(ca1.w, invA, sa7);

        // Per-row label weight via shuffle (no memory access).
        const float wb = __shfl_sync(0xffffffffu, wb_mine, i);
        const float c  = dtp * (invV * invA);
        c_all += c;
        c_pos = fmaf(c, wb, c_pos);

        // Rotate buffers (renamed away by SSA under full unroll).
        cv0 = pv0; cv1 = pv1; ca0 = pa0; ca1 = pa1;
    }

    // Warp totals for the cosine sums.
    c_all = bfly_add(c_all);
    c_pos = bfly_add(c_pos);

    {
        float4* svp = reinterpret_cast<float4*>(s_sv[w]);
        float4* sap = reinterpret_cast<float4*>(s_sa[w]);
        svp[lane]      = make_float4(sv0, sv1, sv2, sv3);
        svp[lane + 32] = make_float4(sv4, sv5, sv6, sv7);
        sap[lane]      = make_float4(sa0, sa1, sa2, sa3);
        sap[lane + 32] = make_float4(sa4, sa5, sa6, sa7);
        if (lane == 0) { s_cp[w] = c_pos; s_ca[w] = c_all; }
    }
    __syncthreads();

    // <Sv_t, Sa_t> across the 4 warp partials; each thread covers 2 d-columns.
    const int d0 = threadIdx.x;
    const int d1 = threadIdx.x + 128;
    float tv0 = 0.f, ta0 = 0.f, tv1 = 0.f, ta1 = 0.f;
    #pragma unroll
    for (int ww = 0; ww < 4; ++ww) {
        tv0 += s_sv[ww][d0]; ta0 += s_sa[ww][d0];
        tv1 += s_sv[ww][d1]; ta1 += s_sa[ww][d1];
    }
    const float prod = bfly_add(fmaf(tv1, ta1, tv0 * ta0));
    if (lane == 0) s_red[w] = prod;
    __syncthreads();

    // Publish block partials; last block performs the final reduce.
    if (threadIdx.x == 0) {
        float cr = 0.f, cpt = 0.f, cat = 0.f;
        #pragma unroll
        for (int ww = 0; ww < 4; ++ww) {
            cr  += s_red[ww];
            cpt += s_cp[ww];
            cat += s_ca[ww];
        }
        g_cr[t] = cr;
        g_cp[t] = cpt;
        g_ca[t] = cat;
        __threadfence();
        const unsigned old = atomicAdd(&g_done, 1u);
        s_last = (old == NBLK - 1) ? 1 : 0;
    }
    __syncthreads();
    if (!s_last) return;

    // ---- Final reduction (one block, deterministic order) ----
    {
        float cr = 0.f, cpr = 0.f, car = 0.f;
        #pragma unroll
        for (int k = 0; k < NBLK / 128; ++k) {
            const int i = threadIdx.x + k * 128;
            cr += g_cr[i]; cpr += g_cp[i]; car += g_ca[i];
        }
        cr  = bfly_add(cr);
        cpr = bfly_add(cpr);
        car = bfly_add(car);
        if (lane == 0) { s_red[w] = cr; s_cp[w] = cpr; s_ca[w] = car; }
        __syncthreads();

        if (threadIdx.x == 0) {
            float Cr = 0.f, Sp = 0.f, Sa = 0.f;
            #pragma unroll
            for (int ww = 0; ww < 4; ++ww) { Cr += s_red[ww]; Sp += s_cp[ww]; Sa += s_ca[ww]; }
            const float Sn = Sa - Sp;

            int npos = 0;
            for (int b = 0; b < Bb; ++b) npos += (labels[b] == 0) ? 1 : 0;
            const float fpos = (float)npos;
            const float fneg = (float)(Bb - npos);

            const float loss_pos = 2.0f * (fpos * (float)Tt - Sp);
            const float loss_neg = 2.0f * Sn + (Cr - Sa) / (float)Tt;

            const float cnt_pos = fpos * (float)Tt;
            const float cnt_neg = fneg * (float)Tt + (float)(Bb * (Bb - 1));

            float loss = 0.f;
            if (cnt_pos > 0.f) loss += loss_pos / fmaxf(cnt_pos, 1.0f);
            if (cnt_neg > 0.f) loss += loss_neg / fmaxf(cnt_neg, 1.0f);
            out[0] = loss;

            g_done = 0;   // self-reset for next (graph-replayed) call
        }
    }
}

extern "C" void kernel_launch(void* const* d_in, const int* in_sizes, int n_in,
                              void* d_out, int out_size)
{
    const float*     fv     = (const float*)d_in[0];
    const float*     fa     = (const float*)d_in[1];
    const long long* labels = (const long long*)d_in[2];
    float*           out    = (float*)d_out;

    (void)in_sizes; (void)n_in; (void)out_size;

    cmfm_fused<<<NBLK, 128>>>(fv, fa, labels, out);
}

// round 13
// speedup vs baseline: 1.1217x; 1.0118x over previous
#include <cuda_runtime.h>

// CMFMLoss: B=64, T=1024, D=256. Single fused streaming kernel.
// Identity: sum_{i!=j} cross_cos[i,j]
//   = (1/T) * [ sum_t <sum_i vn[i,t,:], sum_j an[j,t,:]>  -  sum_{b,t} cos_bt ]
// R9 shape (128 thr, 4 warps x 16 rows, depth-1 register pipeline) with
// __ldcs streaming loads (data is read exactly once -> evict-first policy).

#define Bb 64
#define Tt 1024
#define Dd 256
#define NBLK 1024
#define EPS2 1e-16f

__device__ float    g_cr[NBLK];
__device__ float    g_cp[NBLK];
__device__ float    g_ca[NBLK];
__device__ unsigned g_done = 0;

__device__ __forceinline__ float dot8(const float4& x0, const float4& x1,
                                      const float4& y0, const float4& y1) {
    float s = x0.x * y0.x;
    s = fmaf(x0.y, y0.y, s); s = fmaf(x0.z, y0.z, s); s = fmaf(x0.w, y0.w, s);
    s = fmaf(x1.x, y1.x, s); s = fmaf(x1.y, y1.y, s);
    s = fmaf(x1.z, y1.z, s); s = fmaf(x1.w, y1.w, s);
    return s;
}

__device__ __forceinline__ float bfly_add(float v) {
    #pragma unroll
    for (int off = 16; off > 0; off >>= 1)
        v += __shfl_xor_sync(0xffffffffu, v, off);
    return v;
}

__global__ void __launch_bounds__(128, 7)
cmfm_fused(const float* __restrict__ fv,
           const float* __restrict__ fa,
           const long long* __restrict__ labels,
           float* __restrict__ out)
{
    const int t    = blockIdx.x;
    const int lane = threadIdx.x & 31;
    const int w    = threadIdx.x >> 5;   // warp 0..3

    __shared__ float s_sv[4][Dd];
    __shared__ float s_sa[4][Dd];
    __shared__ float s_cp[4];
    __shared__ float s_ca[4];
    __shared__ float s_red[4];
    __shared__ int   s_last;

    // One label LDG per lane; lane j holds weight of row (w*16 + (j&15)).
    const float wb_mine = (labels[w * 16 + (lane & 15)] == 0) ? 1.0f : 0.0f;

    float sv0=0.f,sv1=0.f,sv2=0.f,sv3=0.f,sv4=0.f,sv5=0.f,sv6=0.f,sv7=0.f;
    float sa0=0.f,sa1=0.f,sa2=0.f,sa3=0.f,sa4=0.f,sa5=0.f,sa6=0.f,sa7=0.f;
    float c_all = 0.f, c_pos = 0.f;     // per-lane partial cosine sums

    const size_t row0 = ((size_t)(w * 16) * Tt + t) * Dd;
    const size_t rstep = (size_t)Tt * Dd;   // +1 in b

    // Prologue: load row 0 (streaming, evict-first).
    const float4* vp = reinterpret_cast<const float4*>(fv + row0);
    const float4* ap = reinterpret_cast<const float4*>(fa + row0);
    float4 cv0 = __ldcs(vp + lane), cv1 = __ldcs(vp + lane + 32);
    float4 ca0 = __ldcs(ap + lane), ca1 = __ldcs(ap + lane + 32);

    #pragma unroll
    for (int i = 0; i < 16; ++i) {
        float4 pv0, pv1, pa0, pa1;
        if (i < 15) {
            const float4* vn_ = reinterpret_cast<const float4*>(fv + row0 + (size_t)(i + 1) * rstep);
            const float4* an_ = reinterpret_cast<const float4*>(fa + row0 + (size_t)(i + 1) * rstep);
            pv0 = __ldcs(vn_ + lane); pv1 = __ldcs(vn_ + lane + 32);
            pa0 = __ldcs(an_ + lane); pa1 = __ldcs(an_ + lane + 32);
        }

        float nv = dot8(cv0, cv1, cv0, cv1);
        float na = dot8(ca0, ca1, ca0, ca1);
        const float dtp = dot8(cv0, cv1, ca0, ca1);   // per-lane partial

        #pragma unroll
        for (int off = 16; off > 0; off >>= 1) {
            nv += __shfl_xor_sync(0xffffffffu, nv, off);
            na += __shfl_xor_sync(0xffffffffu, na, off);
        }

        const float invV = rsqrtf(fmaxf(nv, EPS2));
        const float invA = rsqrtf(fmaxf(na, EPS2));

        sv0 = fmaf(cv0.x, invV, sv0); sv1 = fmaf(cv0.y, invV, sv1);
        sv2 = fmaf(cv0.z, invV, sv2); sv3 = fmaf(cv0.w, invV, sv3);
        sv4 = fmaf(cv1.x, invV, sv4); sv5 = fmaf(cv1.y, invV, sv5);
        sv6 = fmaf(cv1.z, invV, sv6); sv7 = fmaf(cv1.w, invV, sv7);
        sa0 = fmaf(ca0.x, invA, sa0); sa1 = fmaf(ca0.y, invA, sa1);
        sa2 = fmaf(ca0.z, invA, sa2); sa3 = fmaf(ca0.w, invA, sa3);
        sa4 = fmaf(ca1.x, invA, sa4); sa5 = fmaf(ca1.y, invA, sa5);
        sa6 = fmaf(ca1.z, invA, sa6); sa7 = fmaf(ca1.w, invA, sa7);

        // Per-row label weight via shuffle (no memory access).
        const float wb = __shfl_sync(0xffffffffu, wb_mine, i);
        const float c  = dtp * (invV * invA);
        c_all += c;
        c_pos = fmaf(c, wb, c_pos);

        // Rotate buffers (renamed away by SSA under full unroll).
        cv0 = pv0; cv1 = pv1; ca0 = pa0; ca1 = pa1;
    }

    // Warp totals for the cosine sums.
    c_all = bfly_add(c_all);
    c_pos = bfly_add(c_pos);

    {
        float4* svp = reinterpret_cast<float4*>(s_sv[w]);
        float4* sap = reinterpret_cast<float4*>(s_sa[w]);
        svp[lane]      = make_float4(sv0, sv1, sv2, sv3);
        svp[lane + 32] = make_float4(sv4, sv5, sv6, sv7);
        sap[lane]      = make_float4(sa0, sa1, sa2, sa3);
        sap[lane + 32] = make_float4(sa4, sa5, sa6, sa7);
        if (lane == 0) { s_cp[w] = c_pos; s_ca[w] = c_all; }
    }
    __syncthreads();

    // <Sv_t, Sa_t> across the 4 warp partials; each thread covers 2 d-columns.
    const int d0 = threadIdx.x;
    const int d1 = threadIdx.x + 128;
    float tv0 = 0.f, ta0 = 0.f, tv1 = 0.f, ta1 = 0.f;
    #pragma unroll
    for (int ww = 0; ww < 4; ++ww) {
        tv0 += s_sv[ww][d0]; ta0 += s_sa[ww][d0];
        tv1 += s_sv[ww][d1]; ta1 += s_sa[ww][d1];
    }
    const float prod = bfly_add(fmaf(tv1, ta1, tv0 * ta0));
    if (lane == 0) s_red[w] = prod;
    __syncthreads();

    // Publish block partials; last block performs the final reduce.
    if (threadIdx.x == 0) {
        float cr = 0.f, cpt = 0.f, cat = 0.f;
        #pragma unroll
        for (int ww = 0; ww < 4; ++ww) {
            cr  += s_red[ww];
            cpt += s_cp[ww];
            cat += s_ca[ww];
        }
        g_cr[t] = cr;
        g_cp[t] = cpt;
        g_ca[t] = cat;
        __threadfence();
        const unsigned old = atomicAdd(&g_done, 1u);
        s_last = (old == NBLK - 1) ? 1 : 0;
    }
    __syncthreads();
    if (!s_last) return;

    // ---- Final reduction (one block, deterministic order) ----
    {
        float cr = 0.f, cpr = 0.f, car = 0.f;
        #pragma unroll
        for (int k = 0; k < NBLK / 128; ++k) {
            const int i = threadIdx.x + k * 128;
            cr += g_cr[i]; cpr += g_cp[i]; car += g_ca[i];
        }
        cr  = bfly_add(cr);
        cpr = bfly_add(cpr);
        car = bfly_add(car);
        if (lane == 0) { s_red[w] = cr; s_cp[w] = cpr; s_ca[w] = car; }
        __syncthreads();

        if (threadIdx.x == 0) {
            float Cr = 0.f, Sp = 0.f, Sa = 0.f;
            #pragma unroll
            for (int ww = 0; ww < 4; ++ww) { Cr += s_red[ww]; Sp += s_cp[ww]; Sa += s_ca[ww]; }
            const float Sn = Sa - Sp;

            int npos = 0;
            for (int b = 0; b < Bb; ++b) npos += (labels[b] == 0) ? 1 : 0;
            const float fpos = (float)npos;
            const float fneg = (float)(Bb - npos);

            const float loss_pos = 2.0f * (fpos * (float)Tt - Sp);
            const float loss_neg = 2.0f * Sn + (Cr - Sa) / (float)Tt;

            const float cnt_pos = fpos * (float)Tt;
            const float cnt_neg = fneg * (float)Tt + (float)(Bb * (Bb - 1));

            float loss = 0.f;
            if (cnt_pos > 0.f) loss += loss_pos / fmaxf(cnt_pos, 1.0f);
            if (cnt_neg > 0.f) loss += loss_neg / fmaxf(cnt_neg, 1.0f);
            out[0] = loss;

            g_done = 0;   // self-reset for next (graph-replayed) call
        }
    }
}

extern "C" void kernel_launch(void* const* d_in, const int* in_sizes, int n_in,
                              void* d_out, int out_size)
{
    const float*     fv     = (const float*)d_in[0];
    const float*     fa     = (const float*)d_in[1];
    const long long* labels = (const long long*)d_in[2];
    float*           out    = (float*)d_out;

    (void)in_sizes; (void)n_in; (void)out_size;

    cmfm_fused<<<NBLK, 128>>>(fv, fa, labels, out);
}